// round 3
// baseline (speedup 1.0000x reference)
#include <cuda_runtime.h>
#include <cuda_bf16.h>

// Output: out[b,c,h,w] = x[b,c, 2h+o, 2w+p], where (o,p)=divmod(i,2).
// B*C = 24 images, in 2048x2048, out 1024x1024.
// Each thread writes TWO output float4 (8 consecutive out columns),
// reading four contiguous float4 (64B) from the source row and selecting
// lanes by p. Streaming cache hints avoid L2 pollution (pure stream).

static constexpr int H_IN   = 2048;
static constexpr int W_IN   = 2048;
static constexpr int H_OUT  = 1024;
static constexpr int W_OUT  = 1024;
static constexpr int W_OUT4 = W_OUT / 4;               // 256 float4 per out row
static constexpr int W_PAIR = W_OUT4 / 2;              // 128 float4-pairs per out row
static constexpr long IMG_IN = (long)H_IN * W_IN;      // 4,194,304 floats

__global__ void __launch_bounds__(256) slice_stride2_kernel(
    const float* __restrict__ x,
    const int* __restrict__ ip,
    float4* __restrict__ out,
    long totalPairs)
{
    long t = (long)blockIdx.x * blockDim.x + threadIdx.x;
    if (t >= totalPairs) return;

    const int iv = ip[0];
    const int o = (iv >> 1) & 1;
    const int p = iv & 1;

    // t -> (img, out_row, pair). W_PAIR=128 (7 bits), H_OUT=1024 (10 bits).
    const int  pr  = (int)(t & (W_PAIR - 1));
    const int  row = (int)((t >> 7) & (H_OUT - 1));
    const long img = t >> 17;

    const float* src = x + img * IMG_IN + (long)(2 * row + o) * W_IN
                         + (long)pr * 16;

    // 4 independent 128-bit streaming loads (64B contiguous per thread).
    const float4 a = __ldcs((const float4*)(src));
    const float4 b = __ldcs((const float4*)(src + 4));
    const float4 c = __ldcs((const float4*)(src + 8));
    const float4 d = __ldcs((const float4*)(src + 12));

    float4 r0, r1;
    if (p == 0) {
        r0.x = a.x; r0.y = a.z; r0.z = b.x; r0.w = b.z;
        r1.x = c.x; r1.y = c.z; r1.z = d.x; r1.w = d.z;
    } else {
        r0.x = a.y; r0.y = a.w; r0.z = b.y; r0.w = b.w;
        r1.x = c.y; r1.y = c.w; r1.z = d.y; r1.w = d.w;
    }

    float4* dst = out + t * 2;
    __stcs(dst,     r0);
    __stcs(dst + 1, r1);
}

extern "C" void kernel_launch(void* const* d_in, const int* in_sizes, int n_in,
                              void* d_out, int out_size)
{
    const float* x  = (const float*)d_in[0];
    const int*   ip = (const int*)d_in[1];
    float4* out = (float4*)d_out;

    const long totalPairs = (long)out_size / 8;   // 3,145,728
    const int threads = 256;
    const int blocks = (int)((totalPairs + threads - 1) / threads);
    slice_stride2_kernel<<<blocks, threads>>>(x, ip, out, totalPairs);
}

// round 4
// speedup vs baseline: 1.0092x; 1.0092x over previous
#include <cuda_runtime.h>
#include <cuda_bf16.h>

// Output: out[b,c,h,w] = x[b,c, 2h+o, 2w+p], where (o,p)=divmod(i,2).
// B*C = 24 images, in 2048x2048, out 1024x1024.
// R2 structure (best so far): one output float4 per thread, two aligned
// 128-bit loads per thread. Single delta vs R2: streaming hint on the
// store only (__stcs) so the write stream doesn't displace read sectors
// in L2. Loads stay default (no reuse to protect; evict-normal is fine).

static constexpr int H_IN  = 2048;
static constexpr int W_IN  = 2048;
static constexpr int H_OUT = 1024;
static constexpr int W_OUT = 1024;
static constexpr int W_OUT4 = W_OUT / 4;              // 256 float4 per out row
static constexpr long IMG_IN  = (long)H_IN * W_IN;    // 4,194,304 floats

__global__ void __launch_bounds__(256) slice_stride2_kernel(
    const float* __restrict__ x,
    const int* __restrict__ ip,
    float4* __restrict__ out,
    long total4)
{
    long t = (long)blockIdx.x * blockDim.x + threadIdx.x;
    if (t >= total4) return;

    const int iv = ip[0];
    const int o = (iv >> 1) & 1;
    const int p = iv & 1;

    // Decompose t -> (img, out_row, out_col4). W_OUT4=256, H_OUT=1024 pow2.
    const int  w4  = (int)(t & (W_OUT4 - 1));
    const int  row = (int)((t >> 8) & (H_OUT - 1));
    const long img = t >> 18;

    const float* src = x + img * IMG_IN + (long)(2 * row + o) * W_IN + (long)w4 * 8;
    const float4 a = __ldg((const float4*)(src));
    const float4 b = __ldg((const float4*)(src + 4));

    float4 r;
    if (p == 0) { r.x = a.x; r.y = a.z; r.z = b.x; r.w = b.z; }
    else        { r.x = a.y; r.y = a.w; r.z = b.y; r.w = b.w; }

    __stcs(out + t, r);
}

extern "C" void kernel_launch(void* const* d_in, const int* in_sizes, int n_in,
                              void* d_out, int out_size)
{
    const float* x  = (const float*)d_in[0];
    const int*   ip = (const int*)d_in[1];
    float4* out = (float4*)d_out;

    const long total4 = (long)out_size / 4;   // 6,291,456
    const int threads = 256;
    const int blocks = (int)((total4 + threads - 1) / threads);
    slice_stride2_kernel<<<blocks, threads>>>(x, ip, out, total4);
}

// round 5
// speedup vs baseline: 1.0099x; 1.0007x over previous
#include <cuda_runtime.h>
#include <cuda_bf16.h>

// Output: out[b,c,h,w] = x[b,c, 2h+o, 2w+p], where (o,p)=divmod(i,2).
// B*C = 24 images, in 2048x2048, out 1024x1024.
// Each thread: ONE 256-bit load (ld.global.nc.v8.f32, sm_100+) of the 32B
// source span, lane-select by p, one 128-bit streaming store (__stcs).
// Warp-level: a single fully-coalesced 1024B read request per load instr.

static constexpr int H_IN  = 2048;
static constexpr int W_IN  = 2048;
static constexpr int H_OUT = 1024;
static constexpr int W_OUT = 1024;
static constexpr int W_OUT4 = W_OUT / 4;              // 256 float4 per out row
static constexpr long IMG_IN  = (long)H_IN * W_IN;    // 4,194,304 floats

__global__ void __launch_bounds__(256) slice_stride2_kernel(
    const float* __restrict__ x,
    const int* __restrict__ ip,
    float4* __restrict__ out,
    long total4)
{
    long t = (long)blockIdx.x * blockDim.x + threadIdx.x;
    if (t >= total4) return;

    const int iv = ip[0];
    const int o = (iv >> 1) & 1;
    const int p = iv & 1;

    // Decompose t -> (img, out_row, out_col4). W_OUT4=256, H_OUT=1024 pow2.
    const int  w4  = (int)(t & (W_OUT4 - 1));
    const int  row = (int)((t >> 8) & (H_OUT - 1));
    const long img = t >> 18;

    const float* src = x + img * IMG_IN + (long)(2 * row + o) * W_IN + (long)w4 * 8;

    // 256-bit global load (Blackwell): 8 consecutive floats in one LDG.
    float f0, f1, f2, f3, f4, f5, f6, f7;
    asm volatile(
        "ld.global.nc.v8.f32 {%0, %1, %2, %3, %4, %5, %6, %7}, [%8];"
        : "=f"(f0), "=f"(f1), "=f"(f2), "=f"(f3),
          "=f"(f4), "=f"(f5), "=f"(f6), "=f"(f7)
        : "l"(src));

    float4 r;
    if (p == 0) { r.x = f0; r.y = f2; r.z = f4; r.w = f6; }
    else        { r.x = f1; r.y = f3; r.z = f5; r.w = f7; }

    __stcs(out + t, r);
}

extern "C" void kernel_launch(void* const* d_in, const int* in_sizes, int n_in,
                              void* d_out, int out_size)
{
    const float* x  = (const float*)d_in[0];
    const int*   ip = (const int*)d_in[1];
    float4* out = (float4*)d_out;

    const long total4 = (long)out_size / 4;   // 6,291,456
    const int threads = 256;
    const int blocks = (int)((total4 + threads - 1) / threads);
    slice_stride2_kernel<<<blocks, threads>>>(x, ip, out, total4);
}